// round 8
// baseline (speedup 1.0000x reference)
#include <cuda_runtime.h>
#include <cstdint>

// ---------------- problem dims ----------------
#define BATCH 4
#define SEQ   2048
#define DIM   1024
#define BT    (BATCH*SEQ)          // 8192

// ---------------- tile config ----------------
#define BM 128
#define BN 128
#define BK 32
#define NT 256                     // 8 warps, warp tile 64x32
#define SKA 36                     // [row][k] stride (pad 4) for A and NT-B
#define SKB 132                    // [k][n] stride (pad 4) for NN-B (n=128)

// ---------------- scratch (no allocs allowed) ----------------
__device__ float g_Q[BATCH*SEQ*DIM];
__device__ float g_K[BATCH*SEQ*DIM];
__device__ float g_V[BATCH*SEQ*DIM];
__device__ float g_S[(long)BATCH*SEQ*SEQ];

// ---------------- tf32 helpers ----------------
__device__ __forceinline__ uint32_t f2tf(float f) {
    uint32_t u;
    asm("cvt.rna.tf32.f32 %0, %1;" : "=r"(u) : "f"(f));
    return u;
}
__device__ __forceinline__ uint4 f2tf4(float4 v) {
    return make_uint4(f2tf(v.x), f2tf(v.y), f2tf(v.z), f2tf(v.w));
}

__device__ __forceinline__ void mma8(float* c,
                                     uint32_t a0, uint32_t a1, uint32_t a2, uint32_t a3,
                                     uint32_t b0, uint32_t b1)
{
    asm volatile(
        "mma.sync.aligned.m16n8k8.row.col.f32.tf32.tf32.f32 "
        "{%0,%1,%2,%3}, {%4,%5,%6,%7}, {%8,%9}, {%0,%1,%2,%3};"
        : "+f"(c[0]), "+f"(c[1]), "+f"(c[2]), "+f"(c[3])
        : "r"(a0), "r"(a1), "r"(a2), "r"(a3), "r"(b0), "r"(b1));
}

// smem words per buffer
#define A_WORDS   (BM * SKA)               // 4608
#define BNT_WORDS (BN * SKA)               // 4608
#define BNN_WORDS (BK * SKB)               // 4224

// ---- dynamic smem sizes (double-buffered)
#define SMEM_NT ((2*A_WORDS + 2*BNT_WORDS) * 4)   // 73,728 B
#define SMEM_NN ((2*A_WORDS + 2*BNN_WORDS) * 4)   // 70,656 B

// ============================================================
// 128x128x32 TF32 tensor-core GEMM, double-buffered smem (one
// barrier per k-slab), LDG reg-prefetch, STS.128 staging.
// A: [M,K] row-major. BNT=true: B [N,K] row-major (C = A*B^T).
//                     BNT=false: B [K,N] row-major (C = A*B).
// 8 warps 2(M) x 4(N), warp tile 64x32 -> 4 m16 x 4 n8 MMAs.
// ============================================================
template<bool BNT>
__device__ __forceinline__ void gemm_tile(const float* __restrict__ A,
                                          const float* __restrict__ B,
                                          float* __restrict__ C,
                                          int N, int K, float alpha)
{
    extern __shared__ uint32_t smem[];
    uint32_t* Asb[2] = { smem, smem + A_WORDS };
    uint32_t* Bsb[2] = { smem + 2*A_WORDS,
                         smem + 2*A_WORDS + (BNT ? BNT_WORDS : BNN_WORDS) };

    const int tid  = threadIdx.x;
    const int lane = tid & 31;
    const int warp = tid >> 5;
    const int wm   = warp >> 2;        // 0..1
    const int wn   = warp & 3;         // 0..3
    const int lr   = lane >> 2;        // 0..7
    const int lc   = lane & 3;         // 0..3
    const int m0   = blockIdx.y * BM;
    const int n0   = blockIdx.x * BN;

    float acc[4][4][4];
#pragma unroll
    for (int i = 0; i < 4; ++i)
#pragma unroll
        for (int j = 0; j < 4; ++j)
#pragma unroll
            for (int e = 0; e < 4; ++e) acc[i][j][e] = 0.f;

    float4 pfA[4], pfB[4];

    // ---- prologue: LDG tile k0=0 into registers
    {
        const float* Ab = A + (long)m0 * K;
#pragma unroll
        for (int i = 0; i < 4; ++i) {
            int idx = tid + i * NT;         // 0..1023
            int r   = idx >> 3;             // 0..127
            int c4  = idx & 7;
            pfA[i] = *(const float4*)(Ab + (long)r * K + c4 * 4);
        }
        if (BNT) {
            const float* Bb = B + (long)n0 * K;
#pragma unroll
            for (int i = 0; i < 4; ++i) {
                int idx = tid + i * NT;
                int r   = idx >> 3;
                int c4  = idx & 7;
                pfB[i] = *(const float4*)(Bb + (long)r * K + c4 * 4);
            }
        } else {
            const float* Bb = B + n0;
#pragma unroll
            for (int i = 0; i < 4; ++i) {
                int idx = tid + i * NT;     // 0..1023
                int kr  = idx >> 5;         // 0..31
                int c4  = idx & 31;         // 0..31
                pfB[i] = *(const float4*)(Bb + (long)kr * N + c4 * 4);
            }
        }
    }

    int buf = 0;
    for (int k0 = 0; k0 < K; k0 += BK) {
        uint32_t* As = Asb[buf];
        uint32_t* Bs = Bsb[buf];

        // ---- STS.128 staged registers (tf32-converted)
#pragma unroll
        for (int i = 0; i < 4; ++i) {
            int idx = tid + i * NT;
            int r   = idx >> 3;
            int c4  = idx & 7;
            *(uint4*)&As[r * SKA + c4 * 4] = f2tf4(pfA[i]);
        }
        if (BNT) {
#pragma unroll
            for (int i = 0; i < 4; ++i) {
                int idx = tid + i * NT;
                int r   = idx >> 3;
                int c4  = idx & 7;
                *(uint4*)&Bs[r * SKA + c4 * 4] = f2tf4(pfB[i]);
            }
        } else {
#pragma unroll
            for (int i = 0; i < 4; ++i) {
                int idx = tid + i * NT;
                int kr  = idx >> 5;
                int c4  = idx & 31;
                *(uint4*)&Bs[kr * SKB + c4 * 4] = f2tf4(pfB[i]);
            }
        }
        __syncthreads();   // single barrier per slab (double-buffered)

        // ---- prefetch next slab (overlaps MMAs below)
        if (k0 + BK < K) {
            const float* Ab = A + (long)m0 * K + (k0 + BK);
#pragma unroll
            for (int i = 0; i < 4; ++i) {
                int idx = tid + i * NT;
                int r   = idx >> 3;
                int c4  = idx & 7;
                pfA[i] = *(const float4*)(Ab + (long)r * K + c4 * 4);
            }
            if (BNT) {
                const float* Bb = B + (long)n0 * K + (k0 + BK);
#pragma unroll
                for (int i = 0; i < 4; ++i) {
                    int idx = tid + i * NT;
                    int r   = idx >> 3;
                    int c4  = idx & 7;
                    pfB[i] = *(const float4*)(Bb + (long)r * K + c4 * 4);
                }
            } else {
                const float* Bb = B + (long)(k0 + BK) * N + n0;
#pragma unroll
                for (int i = 0; i < 4; ++i) {
                    int idx = tid + i * NT;
                    int kr  = idx >> 5;
                    int c4  = idx & 31;
                    pfB[i] = *(const float4*)(Bb + (long)kr * N + c4 * 4);
                }
            }
        }

        // ---- 4 k8-steps of MMAs (16 MMAs each)
#pragma unroll
        for (int ks = 0; ks < BK; ks += 8) {
            uint32_t af[4][4];
#pragma unroll
            for (int mt = 0; mt < 4; ++mt) {
                int r = wm * 64 + mt * 16 + lr;
                const uint32_t* p = &As[r * SKA + ks + lc];
                af[mt][0] = p[0];
                af[mt][1] = p[8 * SKA];
                af[mt][2] = p[4];
                af[mt][3] = p[8 * SKA + 4];
            }
            uint32_t bf[4][2];
            if (BNT) {
#pragma unroll
                for (int nt = 0; nt < 4; ++nt) {
                    int n = wn * 32 + nt * 8 + lr;
                    const uint32_t* p = &Bs[n * SKA + ks + lc];
                    bf[nt][0] = p[0];
                    bf[nt][1] = p[4];
                }
            } else {
#pragma unroll
                for (int nt = 0; nt < 4; ++nt) {
                    const uint32_t* p = &Bs[(ks + lc) * SKB + wn * 32 + nt * 8 + lr];
                    bf[nt][0] = p[0];
                    bf[nt][1] = p[4 * SKB];
                }
            }
#pragma unroll
            for (int mt = 0; mt < 4; ++mt)
#pragma unroll
                for (int nt = 0; nt < 4; ++nt)
                    mma8(acc[mt][nt],
                         af[mt][0], af[mt][1], af[mt][2], af[mt][3],
                         bf[nt][0], bf[nt][1]);
        }
        buf ^= 1;
    }

    // ---- epilogue: float2 stores, scaled
#pragma unroll
    for (int mt = 0; mt < 4; ++mt) {
#pragma unroll
        for (int nt = 0; nt < 4; ++nt) {
            int r = m0 + wm * 64 + mt * 16 + lr;
            int c = n0 + wn * 32 + nt * 8 + 2 * lc;
            float2 v0 = make_float2(acc[mt][nt][0] * alpha, acc[mt][nt][1] * alpha);
            float2 v1 = make_float2(acc[mt][nt][2] * alpha, acc[mt][nt][3] * alpha);
            *(float2*)&C[(long)r * N + c]       = v0;
            *(float2*)&C[(long)(r + 8) * N + c] = v1;
        }
    }
}

// ============================================================
// Kernels
// ============================================================

__global__ __launch_bounds__(NT, 2)
void qkv_kernel(const float* __restrict__ x,
                const float* __restrict__ Wq,
                const float* __restrict__ Wk,
                const float* __restrict__ Wv)
{
    const float* W = (blockIdx.z == 0) ? Wq : (blockIdx.z == 1) ? Wk : Wv;
    float*       C = (blockIdx.z == 0) ? g_Q : (blockIdx.z == 1) ? g_K : g_V;
    gemm_tile<true>(x, W, C, DIM, DIM, 1.0f);
}

__global__ __launch_bounds__(NT, 2)
void scores_kernel()
{
    long z = blockIdx.z;
    gemm_tile<true>(g_Q + z * (long)SEQ * DIM,
                    g_K + z * (long)SEQ * DIM,
                    g_S + z * (long)SEQ * SEQ,
                    SEQ, DIM, 0.03125f /* 1/sqrt(1024) */);
}

__global__ __launch_bounds__(NT)
void softmax_kernel()
{
    long row = blockIdx.x;
    float4* p = (float4*)(g_S + row * (long)SEQ);
    const int n4 = SEQ / 4;
    int tid = threadIdx.x;
    __shared__ float red[NT];

    float m = -1e30f;
    for (int i = tid; i < n4; i += NT) {
        float4 v = p[i];
        m = fmaxf(m, fmaxf(fmaxf(v.x, v.y), fmaxf(v.z, v.w)));
    }
    red[tid] = m; __syncthreads();
    for (int s = NT / 2; s > 0; s >>= 1) {
        if (tid < s) red[tid] = fmaxf(red[tid], red[tid + s]);
        __syncthreads();
    }
    m = red[0]; __syncthreads();

    float sum = 0.f;
    for (int i = tid; i < n4; i += NT) {
        float4 v = p[i];
        v.x = __expf(v.x - m); v.y = __expf(v.y - m);
        v.z = __expf(v.z - m); v.w = __expf(v.w - m);
        p[i] = v;
        sum += v.x + v.y + v.z + v.w;
    }
    red[tid] = sum; __syncthreads();
    for (int s = NT / 2; s > 0; s >>= 1) {
        if (tid < s) red[tid] += red[tid + s];
        __syncthreads();
    }
    float inv = 1.f / red[0];

    for (int i = tid; i < n4; i += NT) {
        float4 v = p[i];
        v.x *= inv; v.y *= inv; v.z *= inv; v.w *= inv;
        p[i] = v;
    }
}

__global__ __launch_bounds__(NT, 2)
void out_kernel(float* __restrict__ out)
{
    long z = blockIdx.z;
    gemm_tile<false>(g_S + z * (long)SEQ * SEQ,
                     g_V + z * (long)SEQ * DIM,
                     out + z * (long)SEQ * DIM,
                     DIM, SEQ, 1.0f);
}

// ============================================================
// Launch
// ============================================================
extern "C" void kernel_launch(void* const* d_in, const int* in_sizes, int n_in,
                              void* d_out, int out_size)
{
    const float* x  = (const float*)d_in[0];
    const float* Wq = (const float*)d_in[1];
    const float* Wk = (const float*)d_in[2];
    const float* Wv = (const float*)d_in[3];
    float* out = (float*)d_out;

    // idempotent host-side attribute sets (not stream ops; capture-safe)
    cudaFuncSetAttribute(qkv_kernel,    cudaFuncAttributeMaxDynamicSharedMemorySize, SMEM_NT);
    cudaFuncSetAttribute(scores_kernel, cudaFuncAttributeMaxDynamicSharedMemorySize, SMEM_NT);
    cudaFuncSetAttribute(out_kernel,    cudaFuncAttributeMaxDynamicSharedMemorySize, SMEM_NN);

    dim3 blk(NT);

    dim3 g_qkv(DIM / BN, BT / BM, 3);        // (8, 64, 3)
    qkv_kernel<<<g_qkv, blk, SMEM_NT>>>(x, Wq, Wk, Wv);

    dim3 g_sc(SEQ / BN, SEQ / BM, BATCH);    // (16, 16, 4)
    scores_kernel<<<g_sc, blk, SMEM_NT>>>();

    softmax_kernel<<<BT, blk>>>();           // 8192 rows

    dim3 g_out(DIM / BN, SEQ / BM, BATCH);   // (8, 16, 4)
    out_kernel<<<g_out, blk, SMEM_NN>>>(out);
}

// round 11
// speedup vs baseline: 1.8878x; 1.8878x over previous
#include <cuda_runtime.h>
#include <cuda_fp16.h>
#include <cstdint>

// ---------------- problem dims ----------------
#define BATCH 4
#define SEQ   2048
#define DIM   1024
#define BT    (BATCH*SEQ)          // 8192

// ---------------- tile config ----------------
#define BM 128
#define BN 128
#define BK 32
#define NT 256                     // 8 warps, warp tile 64x32
#define SKAH 40                    // smem row stride in halves ([row][k], 32+8 pad)

// ---------------- scratch (no allocs allowed) ----------------
__device__ __half g_Q [BATCH*SEQ*DIM];
__device__ __half g_K [BATCH*SEQ*DIM];
__device__ __half g_V [BATCH*SEQ*DIM];
__device__ __half g_Vt[BATCH*DIM*SEQ];          // V transposed [b][d][s]
__device__ float  g_S [(long)BATCH*SEQ*SEQ];    // logits (fp32 for softmax)
__device__ __half g_P [(long)BATCH*SEQ*SEQ];    // probabilities (fp16)

// ---------------- fp16 mma ----------------
__device__ __forceinline__ void mma16(float* c,
                                      uint32_t a0, uint32_t a1, uint32_t a2, uint32_t a3,
                                      uint32_t b0, uint32_t b1)
{
    asm volatile(
        "mma.sync.aligned.m16n8k16.row.col.f32.f16.f16.f32 "
        "{%0,%1,%2,%3}, {%4,%5,%6,%7}, {%8,%9}, {%0,%1,%2,%3};"
        : "+f"(c[0]), "+f"(c[1]), "+f"(c[2]), "+f"(c[3])
        : "r"(a0), "r"(a1), "r"(a2), "r"(a3), "r"(b0), "r"(b1));
}

// ============================================================
// 128x128x32 FP16 tensor-core NT GEMM (C = A * B^T), R5 structure:
// single-buffered smem, two barriers per slab, LDG reg-prefetch.
// AH/BH: operand source is half (raw copy) vs float (convert at STS).
// CH: output half vs float. alpha scales output.
// 8 warps 2(M) x 4(N), warp tile 64x32 -> 4 m16 x 4 n8k16 MMAs/step.
// ============================================================
template<bool AH, bool BH, bool CH>
__device__ __forceinline__ void gemm_nt(const void* Ap, const void* Bp, void* Cp,
                                        int N, int K, float alpha)
{
    __shared__ __align__(16) __half As[BM * SKAH];
    __shared__ __align__(16) __half Bs[BN * SKAH];

    const float*  Af = (const float*) Ap;
    const __half* Ah = (const __half*)Ap;
    const float*  Bf = (const float*) Bp;
    const __half* Bh = (const __half*)Bp;

    const int tid  = threadIdx.x;
    const int lane = tid & 31;
    const int warp = tid >> 5;
    const int wm   = warp >> 2;        // 0..1
    const int wn   = warp & 3;         // 0..3
    const int lr   = lane >> 2;        // 0..7 (group)
    const int lc   = lane & 3;         // 0..3 (thread-in-group)
    const int m0   = blockIdx.y * BM;
    const int n0   = blockIdx.x * BN;

    float acc[4][4][4];
#pragma unroll
    for (int i = 0; i < 4; ++i)
#pragma unroll
        for (int j = 0; j < 4; ++j)
#pragma unroll
            for (int e = 0; e < 4; ++e) acc[i][j][e] = 0.f;

    // prefetch registers (only the constexpr-selected set is live)
    float4 pfAf[4]; uint4 pfAh[2];
    float4 pfBf[4]; uint4 pfBh[2];

    // ---- prologue: LDG k0=0
    if (!AH) {
#pragma unroll
        for (int i = 0; i < 4; ++i) {
            int idx = tid + i * NT; int r = idx >> 3; int c4 = idx & 7;
            pfAf[i] = *(const float4*)(Af + (long)(m0 + r) * K + c4 * 4);
        }
    } else {
#pragma unroll
        for (int i = 0; i < 2; ++i) {
            int idx = tid + i * NT; int r = idx >> 2; int c8 = idx & 3;
            pfAh[i] = *(const uint4*)(Ah + (long)(m0 + r) * K + c8 * 8);
        }
    }
    if (!BH) {
#pragma unroll
        for (int i = 0; i < 4; ++i) {
            int idx = tid + i * NT; int r = idx >> 3; int c4 = idx & 7;
            pfBf[i] = *(const float4*)(Bf + (long)(n0 + r) * K + c4 * 4);
        }
    } else {
#pragma unroll
        for (int i = 0; i < 2; ++i) {
            int idx = tid + i * NT; int r = idx >> 2; int c8 = idx & 3;
            pfBh[i] = *(const uint4*)(Bh + (long)(n0 + r) * K + c8 * 8);
        }
    }

    for (int k0 = 0; k0 < K; k0 += BK) {
        // ---- STS staged tiles
        if (!AH) {
#pragma unroll
            for (int i = 0; i < 4; ++i) {
                int idx = tid + i * NT; int r = idx >> 3; int c4 = idx & 7;
                __half2 h0 = __floats2half2_rn(pfAf[i].x, pfAf[i].y);
                __half2 h1 = __floats2half2_rn(pfAf[i].z, pfAf[i].w);
                uint2 u; u.x = *(uint32_t*)&h0; u.y = *(uint32_t*)&h1;
                *(uint2*)&As[r * SKAH + c4 * 4] = u;
            }
        } else {
#pragma unroll
            for (int i = 0; i < 2; ++i) {
                int idx = tid + i * NT; int r = idx >> 2; int c8 = idx & 3;
                *(uint4*)&As[r * SKAH + c8 * 8] = pfAh[i];
            }
        }
        if (!BH) {
#pragma unroll
            for (int i = 0; i < 4; ++i) {
                int idx = tid + i * NT; int r = idx >> 3; int c4 = idx & 7;
                __half2 h0 = __floats2half2_rn(pfBf[i].x, pfBf[i].y);
                __half2 h1 = __floats2half2_rn(pfBf[i].z, pfBf[i].w);
                uint2 u; u.x = *(uint32_t*)&h0; u.y = *(uint32_t*)&h1;
                *(uint2*)&Bs[r * SKAH + c4 * 4] = u;
            }
        } else {
#pragma unroll
            for (int i = 0; i < 2; ++i) {
                int idx = tid + i * NT; int r = idx >> 2; int c8 = idx & 3;
                *(uint4*)&Bs[r * SKAH + c8 * 8] = pfBh[i];
            }
        }
        __syncthreads();

        // ---- prefetch next slab (overlaps MMAs)
        if (k0 + BK < K) {
            if (!AH) {
#pragma unroll
                for (int i = 0; i < 4; ++i) {
                    int idx = tid + i * NT; int r = idx >> 3; int c4 = idx & 7;
                    pfAf[i] = *(const float4*)(Af + (long)(m0 + r) * K + (k0 + BK) + c4 * 4);
                }
            } else {
#pragma unroll
                for (int i = 0; i < 2; ++i) {
                    int idx = tid + i * NT; int r = idx >> 2; int c8 = idx & 3;
                    pfAh[i] = *(const uint4*)(Ah + (long)(m0 + r) * K + (k0 + BK) + c8 * 8);
                }
            }
            if (!BH) {
#pragma unroll
                for (int i = 0; i < 4; ++i) {
                    int idx = tid + i * NT; int r = idx >> 3; int c4 = idx & 7;
                    pfBf[i] = *(const float4*)(Bf + (long)(n0 + r) * K + (k0 + BK) + c4 * 4);
                }
            } else {
#pragma unroll
                for (int i = 0; i < 2; ++i) {
                    int idx = tid + i * NT; int r = idx >> 2; int c8 = idx & 3;
                    pfBh[i] = *(const uint4*)(Bh + (long)(n0 + r) * K + (k0 + BK) + c8 * 8);
                }
            }
        }

        // ---- 2 k16-steps of MMAs (16 each)
#pragma unroll
        for (int ks = 0; ks < BK; ks += 16) {
            uint32_t af[4][4];
#pragma unroll
            for (int mt = 0; mt < 4; ++mt) {
                const __half* p = &As[(wm * 64 + mt * 16 + lr) * SKAH + ks + 2 * lc];
                af[mt][0] = *(const uint32_t*)(p);
                af[mt][1] = *(const uint32_t*)(p + 8 * SKAH);
                af[mt][2] = *(const uint32_t*)(p + 8);
                af[mt][3] = *(const uint32_t*)(p + 8 * SKAH + 8);
            }
            uint32_t bf[4][2];
#pragma unroll
            for (int nt = 0; nt < 4; ++nt) {
                const __half* p = &Bs[(wn * 32 + nt * 8 + lr) * SKAH + ks + 2 * lc];
                bf[nt][0] = *(const uint32_t*)(p);
                bf[nt][1] = *(const uint32_t*)(p + 8);
            }
#pragma unroll
            for (int mt = 0; mt < 4; ++mt)
#pragma unroll
                for (int nt = 0; nt < 4; ++nt)
                    mma16(acc[mt][nt],
                          af[mt][0], af[mt][1], af[mt][2], af[mt][3],
                          bf[nt][0], bf[nt][1]);
        }
        __syncthreads();
    }

    // ---- epilogue
#pragma unroll
    for (int mt = 0; mt < 4; ++mt) {
#pragma unroll
        for (int nt = 0; nt < 4; ++nt) {
            int r = m0 + wm * 64 + mt * 16 + lr;
            int c = n0 + wn * 32 + nt * 8 + 2 * lc;
            if (CH) {
                __half* C = (__half*)Cp;
                __half2 h0 = __floats2half2_rn(acc[mt][nt][0] * alpha, acc[mt][nt][1] * alpha);
                __half2 h1 = __floats2half2_rn(acc[mt][nt][2] * alpha, acc[mt][nt][3] * alpha);
                *(__half2*)&C[(long)r * N + c]       = h0;
                *(__half2*)&C[(long)(r + 8) * N + c] = h1;
            } else {
                float* C = (float*)Cp;
                float2 v0 = make_float2(acc[mt][nt][0] * alpha, acc[mt][nt][1] * alpha);
                float2 v1 = make_float2(acc[mt][nt][2] * alpha, acc[mt][nt][3] * alpha);
                *(float2*)&C[(long)r * N + c]       = v0;
                *(float2*)&C[(long)(r + 8) * N + c] = v1;
            }
        }
    }
}

// ============================================================
// Kernels
// ============================================================

// QKV: x[8192,1024] f32 @ W^T f32 -> half Q/K/V. grid (8, 64, 3).
__global__ __launch_bounds__(NT, 2)
void qkv_kernel(const float* __restrict__ x,
                const float* __restrict__ Wq,
                const float* __restrict__ Wk,
                const float* __restrict__ Wv)
{
    const float* W = (blockIdx.z == 0) ? Wq : (blockIdx.z == 1) ? Wk : Wv;
    __half*      C = (blockIdx.z == 0) ? g_Q : (blockIdx.z == 1) ? g_K : g_V;
    gemm_nt<false, false, true>(x, W, C, DIM, DIM, 1.0f);
}

// V transpose: g_V [b][s][d] -> g_Vt [b][d][s]. 64x64 half tiles.
__global__ __launch_bounds__(NT)
void transpose_v_kernel()
{
    __shared__ __align__(16) __half tile[64][68];
    int b  = blockIdx.z;
    int d0 = blockIdx.x * 64;
    int s0 = blockIdx.y * 64;
    const __half* V  = g_V  + (long)b * SEQ * DIM;
    __half*       Vt = g_Vt + (long)b * DIM * SEQ;
    int tid = threadIdx.x;

#pragma unroll
    for (int i = 0; i < 2; ++i) {
        int idx = tid + i * NT;      // 0..511
        int r   = idx >> 3;          // s row 0..63
        int c8  = idx & 7;           // 8-half chunk
        uint4 v = *(const uint4*)&V[(long)(s0 + r) * DIM + d0 + c8 * 8];
        *(uint2*)&tile[r][c8 * 8]     = make_uint2(v.x, v.y);
        *(uint2*)&tile[r][c8 * 8 + 4] = make_uint2(v.z, v.w);
    }
    __syncthreads();
#pragma unroll
    for (int i = 0; i < 2; ++i) {
        int idx = tid + i * NT;
        int d   = idx >> 3;          // d row 0..63
        int c8  = idx & 7;           // s chunk
        __half tmp[8];
#pragma unroll
        for (int j = 0; j < 8; ++j) tmp[j] = tile[c8 * 8 + j][d];
        *(uint4*)&Vt[(long)(d0 + d) * SEQ + s0 + c8 * 8] = *(uint4*)tmp;
    }
}

// S = Q K^T / 32 -> fp32 logits. grid (16, 16, 4).
__global__ __launch_bounds__(NT, 2)
void scores_kernel()
{
    long z = blockIdx.z;
    gemm_nt<true, true, false>(g_Q + z * (long)SEQ * DIM,
                               g_K + z * (long)SEQ * DIM,
                               g_S + z * (long)SEQ * SEQ,
                               SEQ, DIM, 0.03125f);
}

// Row softmax: fp32 logits -> fp16 probabilities.
__global__ __launch_bounds__(NT)
void softmax_kernel()
{
    long row = blockIdx.x;
    const float4* p = (const float4*)(g_S + row * (long)SEQ);
    __half* q = g_P + row * (long)SEQ;
    const int n4 = SEQ / 4;
    int tid = threadIdx.x;
    __shared__ float red[NT];

    float m = -1e30f;
    for (int i = tid; i < n4; i += NT) {
        float4 v = p[i];
        m = fmaxf(m, fmaxf(fmaxf(v.x, v.y), fmaxf(v.z, v.w)));
    }
    red[tid] = m; __syncthreads();
    for (int s = NT / 2; s > 0; s >>= 1) {
        if (tid < s) red[tid] = fmaxf(red[tid], red[tid + s]);
        __syncthreads();
    }
    m = red[0]; __syncthreads();

    float sum = 0.f;
    for (int i = tid; i < n4; i += NT) {
        float4 v = p[i];
        v.x = __expf(v.x - m); v.y = __expf(v.y - m);
        v.z = __expf(v.z - m); v.w = __expf(v.w - m);
        sum += v.x + v.y + v.z + v.w;
        // stash exp values back to g_S to avoid recompute
        ((float4*)(g_S + row * (long)SEQ))[i] = v;
    }
    red[tid] = sum; __syncthreads();
    for (int s = NT / 2; s > 0; s >>= 1) {
        if (tid < s) red[tid] += red[tid + s];
        __syncthreads();
    }
    float inv = 1.f / red[0];

    for (int i = tid; i < n4; i += NT) {
        float4 v = ((const float4*)(g_S + row * (long)SEQ))[i];
        __half2 h0 = __floats2half2_rn(v.x * inv, v.y * inv);
        __half2 h1 = __floats2half2_rn(v.z * inv, v.w * inv);
        uint2 u; u.x = *(uint32_t*)&h0; u.y = *(uint32_t*)&h1;
        *(uint2*)&q[i * 4] = u;
    }
}

// O = P V (NT via Vt): P[q][s] half @ Vt[d][s] half -> fp32 out. grid (8, 16, 4).
__global__ __launch_bounds__(NT, 2)
void out_kernel(float* __restrict__ out)
{
    long z = blockIdx.z;
    gemm_nt<true, true, false>(g_P  + z * (long)SEQ * SEQ,
                               g_Vt + z * (long)DIM * SEQ,
                               out  + z * (long)SEQ * DIM,
                               DIM, SEQ, 1.0f);
}

// ============================================================
// Launch
// ============================================================
extern "C" void kernel_launch(void* const* d_in, const int* in_sizes, int n_in,
                              void* d_out, int out_size)
{
    const float* x  = (const float*)d_in[0];
    const float* Wq = (const float*)d_in[1];
    const float* Wk = (const float*)d_in[2];
    const float* Wv = (const float*)d_in[3];
    float* out = (float*)d_out;

    dim3 blk(NT);

    dim3 g_qkv(DIM / BN, BT / BM, 3);        // (8, 64, 3)
    qkv_kernel<<<g_qkv, blk>>>(x, Wq, Wk, Wv);

    dim3 g_tr(DIM / 64, SEQ / 64, BATCH);    // (16, 32, 4)
    transpose_v_kernel<<<g_tr, blk>>>();

    dim3 g_sc(SEQ / BN, SEQ / BM, BATCH);    // (16, 16, 4)
    scores_kernel<<<g_sc, blk>>>();

    softmax_kernel<<<BT, blk>>>();           // 8192 rows

    dim3 g_out(DIM / BN, SEQ / BM, BATCH);   // (8, 16, 4)
    out_kernel<<<g_out, blk>>>(out);
}

// round 14
// speedup vs baseline: 2.1395x; 1.1333x over previous
#include <cuda_runtime.h>
#include <cuda_fp16.h>
#include <cstdint>

// ---------------- problem dims ----------------
#define BATCH 4
#define SEQ   2048
#define DIM   1024
#define BT    (BATCH*SEQ)          // 8192

// ---------------- tile config ----------------
#define BM 128
#define BN 128
#define BK 32
#define NT 256                     // 8 warps, warp tile 64x32
#define SKAH 40                    // smem row stride in halves (32 + 8 pad, 80B)

// ---------------- scratch (no allocs allowed) ----------------
__device__ __align__(16) __half g_Xh[BT*DIM];            // x in fp16
__device__ __align__(16) __half g_W [3*DIM*DIM];         // Wq|Wk|Wv in fp16
__device__ __align__(16) __half g_Q [BATCH*SEQ*DIM];
__device__ __align__(16) __half g_K [BATCH*SEQ*DIM];
__device__ __align__(16) __half g_V [BATCH*SEQ*DIM];
__device__ __align__(16) __half g_Vt[BATCH*DIM*SEQ];     // V transposed [b][d][s]
__device__ float  g_S [(long)BATCH*SEQ*SEQ];             // logits (fp32 for softmax)
__device__ __align__(16) __half g_P [(long)BATCH*SEQ*SEQ]; // probabilities (fp16)

// ---------------- fp16 mma ----------------
__device__ __forceinline__ void mma16(float* c,
                                      uint32_t a0, uint32_t a1, uint32_t a2, uint32_t a3,
                                      uint32_t b0, uint32_t b1)
{
    asm volatile(
        "mma.sync.aligned.m16n8k16.row.col.f32.f16.f16.f32 "
        "{%0,%1,%2,%3}, {%4,%5,%6,%7}, {%8,%9}, {%0,%1,%2,%3};"
        : "+f"(c[0]), "+f"(c[1]), "+f"(c[2]), "+f"(c[3])
        : "r"(a0), "r"(a1), "r"(a2), "r"(a3), "r"(b0), "r"(b1));
}

// ---------------- cp.async helpers ----------------
__device__ __forceinline__ void cp16(uint32_t smem_addr, const void* gptr) {
    asm volatile("cp.async.cg.shared.global [%0], [%1], 16;\n"
                 :: "r"(smem_addr), "l"(gptr));
}
__device__ __forceinline__ void cp_commit() {
    asm volatile("cp.async.commit_group;\n");
}
__device__ __forceinline__ void cp_wait0() {
    asm volatile("cp.async.wait_group 0;\n");
}

// ============================================================
// 128x128x32 FP16 NT GEMM (C = A * B^T), cp.async 2-stage
// pipeline, ONE barrier per k-slab, zero prefetch registers.
// A: [M,K] half row-major, B: [N,K] half row-major.
// CH: output half vs float. alpha scales output.
// 8 warps 2(M) x 4(N), warp tile 64x32 -> 4 m16 x 4 n8k16 MMAs/step.
// ============================================================
template<bool CH>
__device__ __forceinline__ void gemm_nt_h(const __half* __restrict__ A,
                                          const __half* __restrict__ B,
                                          void* Cp, int N, int K, float alpha)
{
    __shared__ __align__(16) __half As[2][BM * SKAH];
    __shared__ __align__(16) __half Bs[2][BN * SKAH];

    const int tid  = threadIdx.x;
    const int lane = tid & 31;
    const int warp = tid >> 5;
    const int wm   = warp >> 2;        // 0..1
    const int wn   = warp & 3;         // 0..3
    const int lr   = lane >> 2;        // 0..7
    const int lc   = lane & 3;         // 0..3
    const int m0   = blockIdx.y * BM;
    const int n0   = blockIdx.x * BN;

    float acc[4][4][4];
#pragma unroll
    for (int i = 0; i < 4; ++i)
#pragma unroll
        for (int j = 0; j < 4; ++j)
#pragma unroll
            for (int e = 0; e < 4; ++e) acc[i][j][e] = 0.f;

    // issue cp.async loads of one k-slab into buffer `buf`
    auto load_slab = [&](int buf, int k0) {
#pragma unroll
        for (int i = 0; i < 2; ++i) {
            int idx = tid + i * NT;        // 0..511
            int r   = idx >> 2;            // 0..127
            int c   = idx & 3;             // 16B chunk in row
            uint32_t sa = (uint32_t)__cvta_generic_to_shared(&As[buf][r * SKAH + c * 8]);
            cp16(sa, A + (long)(m0 + r) * K + k0 + c * 8);
        }
#pragma unroll
        for (int i = 0; i < 2; ++i) {
            int idx = tid + i * NT;
            int r   = idx >> 2;
            int c   = idx & 3;
            uint32_t sa = (uint32_t)__cvta_generic_to_shared(&Bs[buf][r * SKAH + c * 8]);
            cp16(sa, B + (long)(n0 + r) * K + k0 + c * 8);
        }
    };

    load_slab(0, 0);
    cp_commit();

    int buf = 0;
    for (int k0 = 0; k0 < K; k0 += BK) {
        cp_wait0();          // slab `buf` resident (issued last iteration / prologue)
        __syncthreads();     // visibility + WAR guard (all warps done with buf^1 MMAs)

        if (k0 + BK < K) {
            load_slab(buf ^ 1, k0 + BK);   // overlaps MMAs below in async unit
            cp_commit();
        }

        // ---- 2 k16-steps of MMAs (16 each)
#pragma unroll
        for (int ks = 0; ks < BK; ks += 16) {
            uint32_t af[4][4];
#pragma unroll
            for (int mt = 0; mt < 4; ++mt) {
                const __half* p = &As[buf][(wm * 64 + mt * 16 + lr) * SKAH + ks + 2 * lc];
                af[mt][0] = *(const uint32_t*)(p);
                af[mt][1] = *(const uint32_t*)(p + 8 * SKAH);
                af[mt][2] = *(const uint32_t*)(p + 8);
                af[mt][3] = *(const uint32_t*)(p + 8 * SKAH + 8);
            }
            uint32_t bf[4][2];
#pragma unroll
            for (int nt = 0; nt < 4; ++nt) {
                const __half* p = &Bs[buf][(wn * 32 + nt * 8 + lr) * SKAH + ks + 2 * lc];
                bf[nt][0] = *(const uint32_t*)(p);
                bf[nt][1] = *(const uint32_t*)(p + 8);
            }
#pragma unroll
            for (int mt = 0; mt < 4; ++mt)
#pragma unroll
                for (int nt = 0; nt < 4; ++nt)
                    mma16(acc[mt][nt],
                          af[mt][0], af[mt][1], af[mt][2], af[mt][3],
                          bf[nt][0], bf[nt][1]);
        }
        buf ^= 1;
    }

    // ---- epilogue
#pragma unroll
    for (int mt = 0; mt < 4; ++mt) {
#pragma unroll
        for (int nt = 0; nt < 4; ++nt) {
            int r = m0 + wm * 64 + mt * 16 + lr;
            int c = n0 + wn * 32 + nt * 8 + 2 * lc;
            if (CH) {
                __half* C = (__half*)Cp;
                __half2 h0 = __floats2half2_rn(acc[mt][nt][0] * alpha, acc[mt][nt][1] * alpha);
                __half2 h1 = __floats2half2_rn(acc[mt][nt][2] * alpha, acc[mt][nt][3] * alpha);
                *(__half2*)&C[(long)r * N + c]       = h0;
                *(__half2*)&C[(long)(r + 8) * N + c] = h1;
            } else {
                float* C = (float*)Cp;
                float2 v0 = make_float2(acc[mt][nt][0] * alpha, acc[mt][nt][1] * alpha);
                float2 v1 = make_float2(acc[mt][nt][2] * alpha, acc[mt][nt][3] * alpha);
                *(float2*)&C[(long)r * N + c]       = v0;
                *(float2*)&C[(long)(r + 8) * N + c] = v1;
            }
        }
    }
}

// ============================================================
// Kernels
// ============================================================

// Convert x (fp32) -> g_Xh (fp16). 8192*1024 elems, float4 per thread.
__global__ __launch_bounds__(NT)
void conv_x_kernel(const float* __restrict__ x)
{
    long i = (long)blockIdx.x * NT + threadIdx.x;     // float4 index
    float4 v = ((const float4*)x)[i];
    __half2 h0 = __floats2half2_rn(v.x, v.y);
    __half2 h1 = __floats2half2_rn(v.z, v.w);
    uint2 u; u.x = *(uint32_t*)&h0; u.y = *(uint32_t*)&h1;
    *(uint2*)&g_Xh[i * 4] = u;
}

// Convert Wq|Wk|Wv (fp32) -> g_W (fp16). grid.z selects matrix.
__global__ __launch_bounds__(NT)
void conv_w_kernel(const float* __restrict__ Wq,
                   const float* __restrict__ Wk,
                   const float* __restrict__ Wv)
{
    const float* W = (blockIdx.z == 0) ? Wq : (blockIdx.z == 1) ? Wk : Wv;
    __half* D = g_W + (long)blockIdx.z * DIM * DIM;
    long i = (long)blockIdx.x * NT + threadIdx.x;     // float4 index
    float4 v = ((const float4*)W)[i];
    __half2 h0 = __floats2half2_rn(v.x, v.y);
    __half2 h1 = __floats2half2_rn(v.z, v.w);
    uint2 u; u.x = *(uint32_t*)&h0; u.y = *(uint32_t*)&h1;
    *(uint2*)&D[i * 4] = u;
}

// QKV: g_Xh[8192,1024] @ g_W[z]^T -> half Q/K/V. grid (8, 64, 3).
__global__ __launch_bounds__(NT, 2)
void qkv_kernel()
{
    const __half* W = g_W + (long)blockIdx.z * DIM * DIM;
    __half*       C = (blockIdx.z == 0) ? g_Q : (blockIdx.z == 1) ? g_K : g_V;
    gemm_nt_h<true>(g_Xh, W, C, DIM, DIM, 1.0f);
}

// V transpose: g_V [b][s][d] -> g_Vt [b][d][s]. 64x64 half tiles.
__global__ __launch_bounds__(NT)
void transpose_v_kernel()
{
    __shared__ __align__(16) __half tile[64][68];
    int b  = blockIdx.z;
    int d0 = blockIdx.x * 64;
    int s0 = blockIdx.y * 64;
    const __half* V  = g_V  + (long)b * SEQ * DIM;
    __half*       Vt = g_Vt + (long)b * DIM * SEQ;
    int tid = threadIdx.x;

#pragma unroll
    for (int i = 0; i < 2; ++i) {
        int idx = tid + i * NT;      // 0..511
        int r   = idx >> 3;          // s row 0..63
        int c8  = idx & 7;           // 8-half chunk
        uint4 v = *(const uint4*)&V[(long)(s0 + r) * DIM + d0 + c8 * 8];
        *(uint2*)&tile[r][c8 * 8]     = make_uint2(v.x, v.y);
        *(uint2*)&tile[r][c8 * 8 + 4] = make_uint2(v.z, v.w);
    }
    __syncthreads();
#pragma unroll
    for (int i = 0; i < 2; ++i) {
        int idx = tid + i * NT;
        int d   = idx >> 3;          // d row 0..63
        int c8  = idx & 7;           // s chunk
        __half tmp[8];
#pragma unroll
        for (int j = 0; j < 8; ++j) tmp[j] = tile[c8 * 8 + j][d];
        *(uint4*)&Vt[(long)(d0 + d) * SEQ + s0 + c8 * 8] = *(uint4*)tmp;
    }
}

// S = Q K^T / 32 -> fp32 logits. grid (16, 16, 4).
__global__ __launch_bounds__(NT, 2)
void scores_kernel()
{
    long z = blockIdx.z;
    gemm_nt_h<false>(g_Q + z * (long)SEQ * DIM,
                     g_K + z * (long)SEQ * DIM,
                     g_S + z * (long)SEQ * SEQ,
                     SEQ, DIM, 0.03125f);
}

// Row softmax: fp32 logits -> fp16 probabilities.
__global__ __launch_bounds__(NT)
void softmax_kernel()
{
    long row = blockIdx.x;
    const float4* p = (const float4*)(g_S + row * (long)SEQ);
    __half* q = g_P + row * (long)SEQ;
    const int n4 = SEQ / 4;
    int tid = threadIdx.x;
    __shared__ float red[NT];

    float m = -1e30f;
    for (int i = tid; i < n4; i += NT) {
        float4 v = p[i];
        m = fmaxf(m, fmaxf(fmaxf(v.x, v.y), fmaxf(v.z, v.w)));
    }
    red[tid] = m; __syncthreads();
    for (int s = NT / 2; s > 0; s >>= 1) {
        if (tid < s) red[tid] = fmaxf(red[tid], red[tid + s]);
        __syncthreads();
    }
    m = red[0]; __syncthreads();

    float sum = 0.f;
    for (int i = tid; i < n4; i += NT) {
        float4 v = p[i];
        v.x = __expf(v.x - m); v.y = __expf(v.y - m);
        v.z = __expf(v.z - m); v.w = __expf(v.w - m);
        sum += v.x + v.y + v.z + v.w;
        ((float4*)(g_S + row * (long)SEQ))[i] = v;
    }
    red[tid] = sum; __syncthreads();
    for (int s = NT / 2; s > 0; s >>= 1) {
        if (tid < s) red[tid] += red[tid + s];
        __syncthreads();
    }
    float inv = 1.f / red[0];

    for (int i = tid; i < n4; i += NT) {
        float4 v = ((const float4*)(g_S + row * (long)SEQ))[i];
        __half2 h0 = __floats2half2_rn(v.x * inv, v.y * inv);
        __half2 h1 = __floats2half2_rn(v.z * inv, v.w * inv);
        uint2 u; u.x = *(uint32_t*)&h0; u.y = *(uint32_t*)&h1;
        *(uint2*)&q[i * 4] = u;
    }
}

// O = P V (NT via Vt): P[q][s] half @ Vt[d][s] half -> fp32 out. grid (8, 16, 4).
__global__ __launch_bounds__(NT, 2)
void out_kernel(float* __restrict__ out)
{
    long z = blockIdx.z;
    gemm_nt_h<false>(g_P  + z * (long)SEQ * SEQ,
                     g_Vt + z * (long)DIM * SEQ,
                     out  + z * (long)SEQ * DIM,
                     DIM, SEQ, 1.0f);
}

// ============================================================
// Launch
// ============================================================
extern "C" void kernel_launch(void* const* d_in, const int* in_sizes, int n_in,
                              void* d_out, int out_size)
{
    const float* x  = (const float*)d_in[0];
    const float* Wq = (const float*)d_in[1];
    const float* Wk = (const float*)d_in[2];
    const float* Wv = (const float*)d_in[3];
    float* out = (float*)d_out;

    dim3 blk(NT);

    conv_x_kernel<<<(BT * DIM / 4) / NT, blk>>>(x);              // 8192 blocks
    conv_w_kernel<<<dim3((DIM * DIM / 4) / NT, 1, 3), blk>>>(Wq, Wk, Wv);

    dim3 g_qkv(DIM / BN, BT / BM, 3);        // (8, 64, 3)
    qkv_kernel<<<g_qkv, blk>>>();

    dim3 g_tr(DIM / 64, SEQ / 64, BATCH);    // (16, 32, 4)
    transpose_v_kernel<<<g_tr, blk>>>();

    dim3 g_sc(SEQ / BN, SEQ / BM, BATCH);    // (16, 16, 4)
    scores_kernel<<<g_sc, blk>>>();

    softmax_kernel<<<BT, blk>>>();           // 8192 rows

    dim3 g_out(DIM / BN, SEQ / BM, BATCH);   // (8, 16, 4)
    out_kernel<<<g_out, blk>>>(out);
}